// round 6
// baseline (speedup 1.0000x reference)
#include <cuda_runtime.h>
#include <cuda_bf16.h>
#include <cstdint>

#define NB 8
#define LQ 1024
#define LK 8192
#define DIMD 256
#define DC 128
#define FEPS 1e-6f
#define ONE_MEPS (1.0f - 1e-6f)

// -------------------- device scratch (no allocs allowed) --------------------
__device__ __nv_bfloat16 g_G[DC * DC];                 // W^T W, bf16, row-major
__device__ __nv_bfloat16 g_qp[NB * LQ * DC];           // q' = q @ W_up, bf16
__device__ float2 g_qinfo[NB * LQ];                    // (q_sq, 1-min(q_sq,1-eps))
__device__ __nv_bfloat16 g_kc[(size_t)NB * LK * DC];   // dequantized k_c, bf16
__device__ float2 g_kinfo[NB * LK];                    // (k_sq, 1-min(k_sq,1-eps))

// -------------------- helpers --------------------
static __device__ __forceinline__ uint32_t smem_u32(const void* p) {
    uint32_t a;
    asm("{ .reg .u64 t; cvta.to.shared.u64 t, %1; cvt.u32.u64 %0, t; }" : "=r"(a) : "l"(p));
    return a;
}

#define LDSM4(r0, r1, r2, r3, a) \
    asm volatile("ldmatrix.sync.aligned.m8n8.x4.shared.b16 {%0,%1,%2,%3}, [%4];" \
                 : "=r"(r0), "=r"(r1), "=r"(r2), "=r"(r3) : "r"(a))

#define MMA16816(c, a0, a1, a2, a3, b0, b1) \
    asm volatile("mma.sync.aligned.m16n8k16.row.col.f32.bf16.bf16.f32 " \
                 "{%0,%1,%2,%3},{%4,%5,%6,%7},{%8,%9},{%0,%1,%2,%3};" \
                 : "+f"((c)[0]), "+f"((c)[1]), "+f"((c)[2]), "+f"((c)[3]) \
                 : "r"(a0), "r"(a1), "r"(a2), "r"(a3), "r"(b0), "r"(b1))

static __device__ __forceinline__ uint32_t pack_bf16(float a, float b) {
    __nv_bfloat162 h = __floats2bfloat162_rn(a, b);
    return *reinterpret_cast<uint32_t*>(&h);
}

// -------------------- SMEM layout --------------------
// Tiles stored k-major: 128 rows x 128 bf16, row stride 272B (16B pad) ->
// ldmatrix bank offset = 4*row mod 32: conflict-free.
#define TSTRIDE 272
#define OFF_A 0                       // 34816 B
#define OFF_B 34816                   // 34816 B
#define OFF_INFO 69632                // 1024 B
#define SMEM_DYN 70656

// 128x128x128 bf16 GEMM, 8 warps each 16 rows. acc[64] = 16 n-tiles x 4.
static __device__ __forceinline__ void gemm128(uint32_t aBase, uint32_t bBase,
                                               int wid, int lane, float* acc) {
    uint32_t aAddr = aBase + (uint32_t)(wid * 16 + (lane & 15)) * TSTRIDE +
                     (uint32_t)((lane >> 4) << 4);
    uint32_t bAddr = bBase + (uint32_t)((lane & 7) + ((lane >> 4) << 3)) * TSTRIDE +
                     (uint32_t)(((lane >> 3) & 1) << 4);
#pragma unroll
    for (int kk = 0; kk < 8; kk++) {
        uint32_t a0, a1, a2, a3;
        LDSM4(a0, a1, a2, a3, aAddr + kk * 32);
#pragma unroll
        for (int nt2 = 0; nt2 < 8; nt2++) {
            uint32_t b0, b1, b2, b3;
            LDSM4(b0, b1, b2, b3, bAddr + nt2 * (16 * TSTRIDE) + kk * 32);
            MMA16816(acc + nt2 * 8, a0, a1, a2, a3, b0, b1);
            MMA16816(acc + nt2 * 8 + 4, a0, a1, a2, a3, b2, b3);
        }
    }
}

static __device__ __forceinline__ float hdist(float qk, float qs, float aq, float2 ki) {
    float diff = fmaxf(fmaf(qk, -2.f, qs + ki.x), 0.f);
    float den = fmaf(aq, ki.y, FEPS);
    float x = __fdividef(diff + diff, den) + 1.f;
    float arg = (x > 100.f) ? (x + x)
                            : (x + sqrtf(fmaxf(fmaf(x, x, -1.f), 0.f)));
    return __logf(arg);
}

// ==================== kernel 1: G = W^T W (bf16) ====================
__global__ void prep_G_kernel(const float* __restrict__ W) {
    int idx = blockIdx.x * 256 + threadIdx.x;  // 16384 entries
    int c = idx >> 7, c2 = idx & 127;
    float s = 0.f;
#pragma unroll 4
    for (int d = 0; d < DIMD; d++) s = fmaf(W[d * DC + c], W[d * DC + c2], s);
    g_G[idx] = __float2bfloat16(s);
}

// ==================== kernel 2: q' = q @ W_up (bf16), q_sq (fp32 exact) ====================
__global__ void __launch_bounds__(128) prep_q_kernel(const float* __restrict__ q,
                                                     const float* __restrict__ W) {
    __shared__ float qs[8][DIMD];
    __shared__ float red[32];
    const int t = threadIdx.x;
    const int row0 = blockIdx.x * 8;
    for (int i = t; i < 8 * DIMD; i += 128) qs[i >> 8][i & 255] = q[(size_t)row0 * DIMD + i];
    __syncthreads();
    float acc[8] = {0.f, 0.f, 0.f, 0.f, 0.f, 0.f, 0.f, 0.f};
#pragma unroll 4
    for (int d = 0; d < DIMD; d++) {
        float w = W[d * DC + t];
#pragma unroll
        for (int r = 0; r < 8; r++) acc[r] = fmaf(qs[r][d], w, acc[r]);
    }
#pragma unroll
    for (int r = 0; r < 8; r++) g_qp[(size_t)(row0 + r) * DC + t] = __float2bfloat16(acc[r]);
#pragma unroll
    for (int r = 0; r < 8; r++) {
        float v = qs[r][t] * qs[r][t] + qs[r][t + 128] * qs[r][t + 128];
#pragma unroll
        for (int o = 16; o > 0; o >>= 1) v += __shfl_down_sync(0xffffffffu, v, o);
        if ((t & 31) == 0) red[r * 4 + (t >> 5)] = v;
    }
    __syncthreads();
    if (t < 8) {
        float s = red[t * 4] + red[t * 4 + 1] + red[t * 4 + 2] + red[t * 4 + 3];
        g_qinfo[row0 + t] = make_float2(s, 1.f - fminf(s, ONE_MEPS));
    }
}

// ==================== kernel 3: dequant k_c + k_sq = kc^T G kc (mma.sync) ====================
__global__ void __launch_bounds__(256) prep_k_kernel(const int* __restrict__ kq,
                                                     const float* __restrict__ ksc,
                                                     const float* __restrict__ kz) {
    extern __shared__ char sm[];
    const int t = threadIdx.x, wid = t >> 5, lane = t & 31;
    const int b = blockIdx.x >> 6;
    const int kt = blockIdx.x & 63;
    const size_t rowbase = (size_t)b * LK + (size_t)kt * 128;

    float* scs = (float*)(sm + OFF_INFO);
    float* zrs = (float*)(sm + OFF_INFO + 512);
    if (t < 128) {
        scs[t] = ksc[b * DC + t];
        zrs[t] = kz[b * DC + t];
    }
    __syncthreads();

    // G -> OFF_B, dequant kq -> OFF_A + g_kc (both padded-linear)
#pragma unroll
    for (int i = 0; i < 8; i++) {
        int ci = t + i * 256;
        int row = ci >> 4, c16 = ci & 15;
        *(uint4*)(sm + OFF_B + row * TSTRIDE + c16 * 16) =
            *(const uint4*)((const char*)g_G + (size_t)row * 256 + (size_t)c16 * 16);
        const int4* src = (const int4*)(kq + (rowbase + row) * DC + c16 * 8);
        int4 v0 = src[0], v1 = src[1];
        int c0 = c16 * 8;
        float f0 = ((float)v0.x - zrs[c0 + 0]) * scs[c0 + 0];
        float f1 = ((float)v0.y - zrs[c0 + 1]) * scs[c0 + 1];
        float f2 = ((float)v0.z - zrs[c0 + 2]) * scs[c0 + 2];
        float f3 = ((float)v0.w - zrs[c0 + 3]) * scs[c0 + 3];
        float f4 = ((float)v1.x - zrs[c0 + 4]) * scs[c0 + 4];
        float f5 = ((float)v1.y - zrs[c0 + 5]) * scs[c0 + 5];
        float f6 = ((float)v1.z - zrs[c0 + 6]) * scs[c0 + 6];
        float f7 = ((float)v1.w - zrs[c0 + 7]) * scs[c0 + 7];
        uint4 pk;
        pk.x = pack_bf16(f0, f1); pk.y = pack_bf16(f2, f3);
        pk.z = pack_bf16(f4, f5); pk.w = pack_bf16(f6, f7);
        *(uint4*)(sm + OFF_A + row * TSTRIDE + c16 * 16) = pk;
        *(uint4*)((char*)g_kc + (rowbase + row) * 256 + (size_t)c16 * 16) = pk;
    }
    __syncthreads();

    float acc[64];
#pragma unroll
    for (int i = 0; i < 64; i++) acc[i] = 0.f;
    gemm128(smem_u32(sm + OFF_A), smem_u32(sm + OFF_B), wid, lane, acc);

    // k_sq[row] = sum_c P[row][c] * kc[row][c]
    const int g = lane >> 2, qd = lane & 3;
    const int r0 = wid * 16 + g, r1 = r0 + 8;
    float p0 = 0.f, p1 = 0.f;
#pragma unroll
    for (int nt = 0; nt < 16; nt++) {
        int c0 = nt * 8 + qd * 2;
        __nv_bfloat162 kv0 = *(const __nv_bfloat162*)(sm + OFF_A + r0 * TSTRIDE + c0 * 2);
        __nv_bfloat162 kv1 = *(const __nv_bfloat162*)(sm + OFF_A + r1 * TSTRIDE + c0 * 2);
        float2 f0 = __bfloat1622float2(kv0), f1 = __bfloat1622float2(kv1);
        p0 = fmaf(acc[nt * 4 + 0], f0.x, fmaf(acc[nt * 4 + 1], f0.y, p0));
        p1 = fmaf(acc[nt * 4 + 2], f1.x, fmaf(acc[nt * 4 + 3], f1.y, p1));
    }
    p0 += __shfl_xor_sync(0xffffffffu, p0, 1);
    p0 += __shfl_xor_sync(0xffffffffu, p0, 2);
    p1 += __shfl_xor_sync(0xffffffffu, p1, 1);
    p1 += __shfl_xor_sync(0xffffffffu, p1, 2);
    if (qd == 0) {
        g_kinfo[rowbase + r0] = make_float2(p0, 1.f - fminf(p0, ONE_MEPS));
        g_kinfo[rowbase + r1] = make_float2(p1, 1.f - fminf(p1, ONE_MEPS));
    }
}

// ==================== kernel 4: main GEMM qk + hyperbolic-distance epilogue ====================
__global__ void __launch_bounds__(256) main_kernel(float* __restrict__ out) {
    extern __shared__ char sm[];
    const int t = threadIdx.x, wid = t >> 5, lane = t & 31;
    const int bx = blockIdx.x;
    const int b = bx >> 9;
    const int rem = bx & 511;
    const int kt = rem >> 3;     // 8 consecutive CTAs share the kc tile (L2 reuse)
    const int qt = rem & 7;
    const size_t q0 = (size_t)b * LQ + (size_t)qt * 128;
    const size_t k0 = (size_t)b * LK + (size_t)kt * 128;

#pragma unroll
    for (int i = 0; i < 8; i++) {
        int ci = t + i * 256;
        int row = ci >> 4, c16 = ci & 15;
        *(uint4*)(sm + OFF_A + row * TSTRIDE + c16 * 16) =
            *(const uint4*)((const char*)g_qp + (q0 + row) * 256 + (size_t)c16 * 16);
        *(uint4*)(sm + OFF_B + row * TSTRIDE + c16 * 16) =
            *(const uint4*)((const char*)g_kc + (k0 + row) * 256 + (size_t)c16 * 16);
    }
    if (t < 128) ((float2*)(sm + OFF_INFO))[t] = g_kinfo[k0 + t];
    __syncthreads();

    float acc[64];
#pragma unroll
    for (int i = 0; i < 64; i++) acc[i] = 0.f;
    gemm128(smem_u32(sm + OFF_A), smem_u32(sm + OFF_B), wid, lane, acc);

    const int g = lane >> 2, qd = lane & 3;
    float2 qi0 = g_qinfo[q0 + wid * 16 + g];
    float2 qi1 = g_qinfo[q0 + wid * 16 + g + 8];
    const float2* kinf = (const float2*)(sm + OFF_INFO);
    size_t orow0 = ((size_t)b * LQ + (size_t)qt * 128 + (size_t)(wid * 16 + g)) * LK +
                   (size_t)kt * 128;
    size_t orow1 = orow0 + (size_t)8 * LK;

#pragma unroll
    for (int nt = 0; nt < 16; nt++) {
        int c0 = nt * 8 + qd * 2;
        float2 ki0 = kinf[c0], ki1 = kinf[c0 + 1];
        float d00 = hdist(acc[nt * 4 + 0], qi0.x, qi0.y, ki0);
        float d01 = hdist(acc[nt * 4 + 1], qi0.x, qi0.y, ki1);
        float d10 = hdist(acc[nt * 4 + 2], qi1.x, qi1.y, ki0);
        float d11 = hdist(acc[nt * 4 + 3], qi1.x, qi1.y, ki1);
        *(float2*)(out + orow0 + c0) = make_float2(d00, d01);
        *(float2*)(out + orow1 + c0) = make_float2(d10, d11);
    }
}

// ==================== launch ====================
extern "C" void kernel_launch(void* const* d_in, const int* in_sizes, int n_in,
                              void* d_out, int out_size) {
    const float* q   = (const float*)d_in[0];
    const int*   kq  = (const int*)d_in[1];
    const float* ksc = (const float*)d_in[2];
    const float* kz  = (const float*)d_in[3];
    const float* W   = (const float*)d_in[4];
    float* out = (float*)d_out;

    cudaFuncSetAttribute(prep_k_kernel, cudaFuncAttributeMaxDynamicSharedMemorySize, SMEM_DYN);
    cudaFuncSetAttribute(main_kernel, cudaFuncAttributeMaxDynamicSharedMemorySize, SMEM_DYN);

    prep_G_kernel<<<64, 256>>>(W);
    prep_q_kernel<<<NB * LQ / 8, 128>>>(q, W);
    prep_k_kernel<<<NB * (LK / 128), 256, SMEM_DYN>>>(kq, ksc, kz);
    main_kernel<<<NB * (LQ / 128) * (LK / 128), 256, SMEM_DYN>>>(out);
}

// round 11
// speedup vs baseline: 1.1148x; 1.1148x over previous
#include <cuda_runtime.h>
#include <cuda_bf16.h>
#include <cstdint>

#define NB 8
#define LQ 1024
#define LK 8192
#define DIMD 256
#define DC 128
#define FEPS 1e-6f
#define ONE_MEPS (1.0f - 1e-6f)

// -------------------- device scratch (no allocs allowed) --------------------
__device__ __nv_bfloat16 g_G[DC * DC];                 // W^T W, bf16, row-major
__device__ __nv_bfloat16 g_qp[NB * LQ * DC];           // q' = q @ W_up, bf16
__device__ float2 g_qinfo[NB * LQ];                    // (q_sq, 1-min(q_sq,1-eps))
__device__ __nv_bfloat16 g_kc[(size_t)NB * LK * DC];   // dequantized k_c, bf16
__device__ float2 g_kinfo[NB * LK];                    // (k_sq, 1-min(k_sq,1-eps))

// -------------------- helpers --------------------
static __device__ __forceinline__ uint32_t smem_u32(const void* p) {
    uint32_t a;
    asm("{ .reg .u64 t; cvta.to.shared.u64 t, %1; cvt.u32.u64 %0, t; }" : "=r"(a) : "l"(p));
    return a;
}

#define LDSM4(r0, r1, r2, r3, a) \
    asm volatile("ldmatrix.sync.aligned.m8n8.x4.shared.b16 {%0,%1,%2,%3}, [%4];" \
                 : "=r"(r0), "=r"(r1), "=r"(r2), "=r"(r3) : "r"(a))

#define LDSM4T(r0, r1, r2, r3, a) \
    asm volatile("ldmatrix.sync.aligned.m8n8.x4.trans.shared.b16 {%0,%1,%2,%3}, [%4];" \
                 : "=r"(r0), "=r"(r1), "=r"(r2), "=r"(r3) : "r"(a))

#define MMA16816(c, a0, a1, a2, a3, b0, b1) \
    asm volatile("mma.sync.aligned.m16n8k16.row.col.f32.bf16.bf16.f32 " \
                 "{%0,%1,%2,%3},{%4,%5,%6,%7},{%8,%9},{%0,%1,%2,%3};" \
                 : "+f"((c)[0]), "+f"((c)[1]), "+f"((c)[2]), "+f"((c)[3]) \
                 : "r"(a0), "r"(a1), "r"(a2), "r"(a3), "r"(b0), "r"(b1))

static __device__ __forceinline__ uint32_t pack_bf16(float a, float b) {
    __nv_bfloat162 h = __floats2bfloat162_rn(a, b);
    return *reinterpret_cast<uint32_t*>(&h);
}

// -------------------- SMEM layouts --------------------
// K=128 tiles: 128 rows x 128 bf16, row stride 272B (16B pad) -> ldmatrix conflict-free.
#define TSTRIDE 272
#define OFF_A 0                       // 34816 B
#define OFF_B 34816                   // 34816 B
#define OFF_INFO 69632                // 1024 B
#define SMEM_DYN 70656
// prep_q: A = q tile 128 rows x 256 bf16, stride 528B; W native 256 rows x 128 bf16, stride 272B.
#define QSTRIDE 528
#define QOFF_A 0                      // 128*528 = 67584
#define QOFF_W 67584                  // 256*272 = 69632
#define QOFF_SQ 137216                // float[128]
#define SMEM_Q 137728

// ---- warp-tile GEMM: 32(M) x 64(N) per warp, K = NKK*16, both operands k-major ----
// acc[n*8 + mt*4 + i], n = 0..7 (8-col subtiles), mt = 0..1 (16-row subtiles).
static __device__ __forceinline__ void gemm_wt(uint32_t aBase, uint32_t bBase,
                                               int m0, int n0, int lane, float* acc) {
    uint32_t aAddr0 = aBase + (uint32_t)(m0 + (lane & 15)) * TSTRIDE + (uint32_t)((lane >> 4) << 4);
    uint32_t aAddr1 = aAddr0 + 16 * TSTRIDE;
    uint32_t bAddr = bBase + (uint32_t)(n0 + (lane & 7) + ((lane >> 4) << 3)) * TSTRIDE +
                     (uint32_t)(((lane >> 3) & 1) << 4);
#pragma unroll
    for (int kk = 0; kk < 8; kk++) {
        uint32_t a0, a1, a2, a3, c0, c1, c2, c3;
        LDSM4(a0, a1, a2, a3, aAddr0 + kk * 32);
        LDSM4(c0, c1, c2, c3, aAddr1 + kk * 32);
#pragma unroll
        for (int j = 0; j < 4; j++) {
            uint32_t b0, b1, b2, b3;
            LDSM4(b0, b1, b2, b3, bAddr + j * (16 * TSTRIDE) + kk * 32);
            MMA16816(acc + (2 * j) * 8 + 0, a0, a1, a2, a3, b0, b1);
            MMA16816(acc + (2 * j) * 8 + 4, c0, c1, c2, c3, b0, b1);
            MMA16816(acc + (2 * j + 1) * 8 + 0, a0, a1, a2, a3, b2, b3);
            MMA16816(acc + (2 * j + 1) * 8 + 4, c0, c1, c2, c3, b2, b3);
        }
    }
}

// ---- prep_q GEMM: A = q tile (stride 528, K=256), B = W native row-major via ldmatrix.trans ----
static __device__ __forceinline__ void gemm_qw(uint32_t aBase, uint32_t wBase,
                                               int m0, int n0, int lane, float* acc) {
    uint32_t aAddr0 = aBase + (uint32_t)(m0 + (lane & 15)) * QSTRIDE + (uint32_t)((lane >> 4) << 4);
    uint32_t aAddr1 = aAddr0 + 16 * QSTRIDE;
    uint32_t bAddr = wBase + (uint32_t)(lane & 15) * TSTRIDE + (uint32_t)((lane >> 4) << 4) +
                     (uint32_t)(n0 * 2);
#pragma unroll
    for (int kk = 0; kk < 16; kk++) {
        uint32_t a0, a1, a2, a3, c0, c1, c2, c3;
        LDSM4(a0, a1, a2, a3, aAddr0 + kk * 32);
        LDSM4(c0, c1, c2, c3, aAddr1 + kk * 32);
        uint32_t brow = bAddr + (uint32_t)(kk * 16) * TSTRIDE;
#pragma unroll
        for (int j = 0; j < 4; j++) {
            uint32_t b0, b1, b2, b3;
            LDSM4T(b0, b1, b2, b3, brow + j * 32);
            MMA16816(acc + (2 * j) * 8 + 0, a0, a1, a2, a3, b0, b1);
            MMA16816(acc + (2 * j) * 8 + 4, c0, c1, c2, c3, b0, b1);
            MMA16816(acc + (2 * j + 1) * 8 + 0, a0, a1, a2, a3, b2, b3);
            MMA16816(acc + (2 * j + 1) * 8 + 4, c0, c1, c2, c3, b2, b3);
        }
    }
}

// ---- legacy 8x1 warp tiling (kept for prep_k) ----
static __device__ __forceinline__ void gemm128(uint32_t aBase, uint32_t bBase,
                                               int wid, int lane, float* acc) {
    uint32_t aAddr = aBase + (uint32_t)(wid * 16 + (lane & 15)) * TSTRIDE +
                     (uint32_t)((lane >> 4) << 4);
    uint32_t bAddr = bBase + (uint32_t)((lane & 7) + ((lane >> 4) << 3)) * TSTRIDE +
                     (uint32_t)(((lane >> 3) & 1) << 4);
#pragma unroll
    for (int kk = 0; kk < 8; kk++) {
        uint32_t a0, a1, a2, a3;
        LDSM4(a0, a1, a2, a3, aAddr + kk * 32);
#pragma unroll
        for (int nt2 = 0; nt2 < 8; nt2++) {
            uint32_t b0, b1, b2, b3;
            LDSM4(b0, b1, b2, b3, bAddr + nt2 * (16 * TSTRIDE) + kk * 32);
            MMA16816(acc + nt2 * 8, a0, a1, a2, a3, b0, b1);
            MMA16816(acc + nt2 * 8 + 4, a0, a1, a2, a3, b2, b3);
        }
    }
}

static __device__ __forceinline__ float hdist(float qk, float qs, float aq, float2 ki) {
    float diff = fmaxf(fmaf(qk, -2.f, qs + ki.x), 0.f);
    float den = fmaf(aq, ki.y, FEPS);
    float x = __fdividef(diff + diff, den) + 1.f;
    float arg = (x > 100.f) ? (x + x)
                            : (x + sqrtf(fmaxf(fmaf(x, x, -1.f), 0.f)));
    return __logf(arg);
}

// ==================== kernel 1: G = W^T W (bf16) ====================
__global__ void prep_G_kernel(const float* __restrict__ W) {
    int idx = blockIdx.x * 256 + threadIdx.x;  // 16384 entries
    int c = idx >> 7, c2 = idx & 127;
    float s = 0.f;
#pragma unroll 4
    for (int d = 0; d < DIMD; d++) s = fmaf(W[d * DC + c], W[d * DC + c2], s);
    g_G[idx] = __float2bfloat16(s);
}

// ==================== kernel 2: q' = q @ W_up (tensor), q_sq (fp32 exact) ====================
__global__ void __launch_bounds__(256) prep_q_kernel(const float* __restrict__ q,
                                                     const float* __restrict__ W) {
    extern __shared__ char sm[];
    const int t = threadIdx.x, wid = t >> 5, lane = t & 31;
    const size_t q0 = (size_t)blockIdx.x * 128;
    float* qsq = (float*)(sm + QOFF_SQ);

    if (t < 128) qsq[t] = 0.f;
    __syncthreads();

    // A load: q tile 128 x 256 fp32 -> bf16 (stride 528), accumulate q_sq (fp32 exact).
#pragma unroll 4
    for (int j = 0; j < 32; j++) {
        int ci = t + j * 256;               // float4-chunk index: 64 per row
        int row = ci >> 6, c4 = ci & 63;
        float4 v = *(const float4*)(q + (q0 + row) * DIMD + c4 * 4);
        uint2 pk;
        pk.x = pack_bf16(v.x, v.y);
        pk.y = pack_bf16(v.z, v.w);
        *(uint2*)(sm + QOFF_A + row * QSTRIDE + c4 * 8) = pk;
        float red = v.x * v.x + v.y * v.y + v.z * v.z + v.w * v.w;
#pragma unroll
        for (int o = 16; o > 0; o >>= 1) red += __shfl_down_sync(0xffffffffu, red, o);
        if (lane == 0) atomicAdd(&qsq[row], red);   // all lanes of a warp share one row
    }
    // W load: native row-major 256 x 128 fp32 -> bf16 (stride 272)
#pragma unroll 4
    for (int j = 0; j < 32; j++) {
        int i4 = t + j * 256;               // float4-chunk: 32 per W row
        int d = i4 >> 5, c4 = (i4 & 31) * 4;
        float4 w = *(const float4*)(W + d * DC + c4);
        uint2 pk;
        pk.x = pack_bf16(w.x, w.y);
        pk.y = pack_bf16(w.z, w.w);
        *(uint2*)(sm + QOFF_W + d * TSTRIDE + c4 * 2) = pk;
    }
    __syncthreads();

    if (t < 128) {
        float s = qsq[t];
        g_qinfo[q0 + t] = make_float2(s, 1.f - fminf(s, ONE_MEPS));
    }

    float acc[64];
#pragma unroll
    for (int i = 0; i < 64; i++) acc[i] = 0.f;
    const int wm = wid & 3, wn = wid >> 2;
    const int m0 = wm * 32, n0 = wn * 64;
    gemm_qw(smem_u32(sm + QOFF_A), smem_u32(sm + QOFF_W), m0, n0, lane, acc);

    const int g = lane >> 2, qd = lane & 3;
#pragma unroll
    for (int n = 0; n < 8; n++) {
        int col = n0 + n * 8 + qd * 2;
#pragma unroll
        for (int mt = 0; mt < 2; mt++) {
#pragma unroll
            for (int h = 0; h < 2; h++) {
                int row = m0 + mt * 16 + h * 8 + g;
                int idx = n * 8 + mt * 4 + h * 2;
                *(uint32_t*)((char*)g_qp + (q0 + row) * 256 + col * 2) =
                    pack_bf16(acc[idx], acc[idx + 1]);
            }
        }
    }
}

// ==================== kernel 3: dequant k_c + k_sq = kc^T G kc (mma.sync) ====================
__global__ void __launch_bounds__(256) prep_k_kernel(const int* __restrict__ kq,
                                                     const float* __restrict__ ksc,
                                                     const float* __restrict__ kz) {
    extern __shared__ char sm[];
    const int t = threadIdx.x, wid = t >> 5, lane = t & 31;
    const int b = blockIdx.x >> 6;
    const int kt = blockIdx.x & 63;
    const size_t rowbase = (size_t)b * LK + (size_t)kt * 128;

    float* scs = (float*)(sm + OFF_INFO);
    float* zrs = (float*)(sm + OFF_INFO + 512);
    if (t < 128) {
        scs[t] = ksc[b * DC + t];
        zrs[t] = kz[b * DC + t];
    }
    __syncthreads();

#pragma unroll
    for (int i = 0; i < 8; i++) {
        int ci = t + i * 256;
        int row = ci >> 4, c16 = ci & 15;
        *(uint4*)(sm + OFF_B + row * TSTRIDE + c16 * 16) =
            *(const uint4*)((const char*)g_G + (size_t)row * 256 + (size_t)c16 * 16);
        const int4* src = (const int4*)(kq + (rowbase + row) * DC + c16 * 8);
        int4 v0 = src[0], v1 = src[1];
        int c0 = c16 * 8;
        float f0 = ((float)v0.x - zrs[c0 + 0]) * scs[c0 + 0];
        float f1 = ((float)v0.y - zrs[c0 + 1]) * scs[c0 + 1];
        float f2 = ((float)v0.z - zrs[c0 + 2]) * scs[c0 + 2];
        float f3 = ((float)v0.w - zrs[c0 + 3]) * scs[c0 + 3];
        float f4 = ((float)v1.x - zrs[c0 + 4]) * scs[c0 + 4];
        float f5 = ((float)v1.y - zrs[c0 + 5]) * scs[c0 + 5];
        float f6 = ((float)v1.z - zrs[c0 + 6]) * scs[c0 + 6];
        float f7 = ((float)v1.w - zrs[c0 + 7]) * scs[c0 + 7];
        uint4 pk;
        pk.x = pack_bf16(f0, f1); pk.y = pack_bf16(f2, f3);
        pk.z = pack_bf16(f4, f5); pk.w = pack_bf16(f6, f7);
        *(uint4*)(sm + OFF_A + row * TSTRIDE + c16 * 16) = pk;
        *(uint4*)((char*)g_kc + (rowbase + row) * 256 + (size_t)c16 * 16) = pk;
    }
    __syncthreads();

    float acc[64];
#pragma unroll
    for (int i = 0; i < 64; i++) acc[i] = 0.f;
    gemm128(smem_u32(sm + OFF_A), smem_u32(sm + OFF_B), wid, lane, acc);

    const int g = lane >> 2, qd = lane & 3;
    const int r0 = wid * 16 + g, r1 = r0 + 8;
    float p0 = 0.f, p1 = 0.f;
#pragma unroll
    for (int nt = 0; nt < 16; nt++) {
        int c0 = nt * 8 + qd * 2;
        __nv_bfloat162 kv0 = *(const __nv_bfloat162*)(sm + OFF_A + r0 * TSTRIDE + c0 * 2);
        __nv_bfloat162 kv1 = *(const __nv_bfloat162*)(sm + OFF_A + r1 * TSTRIDE + c0 * 2);
        float2 f0 = __bfloat1622float2(kv0), f1 = __bfloat1622float2(kv1);
        p0 = fmaf(acc[nt * 4 + 0], f0.x, fmaf(acc[nt * 4 + 1], f0.y, p0));
        p1 = fmaf(acc[nt * 4 + 2], f1.x, fmaf(acc[nt * 4 + 3], f1.y, p1));
    }
    p0 += __shfl_xor_sync(0xffffffffu, p0, 1);
    p0 += __shfl_xor_sync(0xffffffffu, p0, 2);
    p1 += __shfl_xor_sync(0xffffffffu, p1, 1);
    p1 += __shfl_xor_sync(0xffffffffu, p1, 2);
    if (qd == 0) {
        g_kinfo[rowbase + r0] = make_float2(p0, 1.f - fminf(p0, ONE_MEPS));
        g_kinfo[rowbase + r1] = make_float2(p1, 1.f - fminf(p1, ONE_MEPS));
    }
}

// ==================== kernel 4: main GEMM qk + hyperbolic-distance epilogue ====================
__global__ void __launch_bounds__(256) main_kernel(float* __restrict__ out) {
    extern __shared__ char sm[];
    const int t = threadIdx.x, wid = t >> 5, lane = t & 31;
    const int bx = blockIdx.x;
    const int b = bx >> 9;
    const int rem = bx & 511;
    const int kt = rem >> 3;     // 8 consecutive CTAs share the kc tile (L2 reuse)
    const int qt = rem & 7;
    const size_t q0 = (size_t)b * LQ + (size_t)qt * 128;
    const size_t k0 = (size_t)b * LK + (size_t)kt * 128;

#pragma unroll
    for (int i = 0; i < 8; i++) {
        int ci = t + i * 256;
        int row = ci >> 4, c16 = ci & 15;
        *(uint4*)(sm + OFF_A + row * TSTRIDE + c16 * 16) =
            *(const uint4*)((const char*)g_qp + (q0 + row) * 256 + (size_t)c16 * 16);
        *(uint4*)(sm + OFF_B + row * TSTRIDE + c16 * 16) =
            *(const uint4*)((const char*)g_kc + (k0 + row) * 256 + (size_t)c16 * 16);
    }
    if (t < 128) ((float2*)(sm + OFF_INFO))[t] = g_kinfo[k0 + t];
    __syncthreads();

    float acc[64];
#pragma unroll
    for (int i = 0; i < 64; i++) acc[i] = 0.f;
    const int wm = wid & 3, wn = wid >> 2;
    const int m0 = wm * 32, n0 = wn * 64;
    gemm_wt(smem_u32(sm + OFF_A), smem_u32(sm + OFF_B), m0, n0, lane, acc);

    const int g = lane >> 2, qd = lane & 3;
    float2 qi[4];
#pragma unroll
    for (int mt = 0; mt < 2; mt++)
#pragma unroll
        for (int h = 0; h < 2; h++)
            qi[mt * 2 + h] = g_qinfo[q0 + m0 + mt * 16 + h * 8 + g];
    const float2* kinf = (const float2*)(sm + OFF_INFO);
    const size_t obase = ((size_t)b * LQ + (size_t)qt * 128) * LK + (size_t)kt * 128;

#pragma unroll
    for (int n = 0; n < 8; n++) {
        int col = n0 + n * 8 + qd * 2;
        float2 ki0 = kinf[col], ki1 = kinf[col + 1];
#pragma unroll
        for (int mt = 0; mt < 2; mt++) {
#pragma unroll
            for (int h = 0; h < 2; h++) {
                int row = m0 + mt * 16 + h * 8 + g;
                int idx = n * 8 + mt * 4 + h * 2;
                float2 qv = qi[mt * 2 + h];
                float d0 = hdist(acc[idx], qv.x, qv.y, ki0);
                float d1 = hdist(acc[idx + 1], qv.x, qv.y, ki1);
                *(float2*)(out + obase + (size_t)row * LK + col) = make_float2(d0, d1);
            }
        }
    }
}

// ==================== launch ====================
extern "C" void kernel_launch(void* const* d_in, const int* in_sizes, int n_in,
                              void* d_out, int out_size) {
    const float* q   = (const float*)d_in[0];
    const int*   kq  = (const int*)d_in[1];
    const float* ksc = (const float*)d_in[2];
    const float* kz  = (const float*)d_in[3];
    const float* W   = (const float*)d_in[4];
    float* out = (float*)d_out;

    cudaFuncSetAttribute(prep_q_kernel, cudaFuncAttributeMaxDynamicSharedMemorySize, SMEM_Q);
    cudaFuncSetAttribute(prep_k_kernel, cudaFuncAttributeMaxDynamicSharedMemorySize, SMEM_DYN);
    cudaFuncSetAttribute(main_kernel, cudaFuncAttributeMaxDynamicSharedMemorySize, SMEM_DYN);

    prep_G_kernel<<<64, 256>>>(W);
    prep_q_kernel<<<NB * LQ / 128, 256, SMEM_Q>>>(q, W);
    prep_k_kernel<<<NB * (LK / 128), 256, SMEM_DYN>>>(kq, ksc, kz);
    main_kernel<<<NB * (LQ / 128) * (LK / 128), 256, SMEM_DYN>>>(out);
}